// round 12
// baseline (speedup 1.0000x reference)
#include <cuda_runtime.h>
#include <cuda_fp16.h>
#include <cstdint>

#define H 64
#define TILE 128
#define NT 128
#define RS 144                  // smem row stride (bytes): 9*16 -> conflict-free ldmatrix
#define L2E 1.4426950408889634f

typedef unsigned long long ull;

// ---- smem layout (bytes) ----
#define OFF_AH   0               // h (fp16)  : 128 x 144 = 18432
#define OFF_W2H  18432           // W2 (fp16) : 64 x 144 = 9216
#define OFF_MH   27648           // M  (fp16) : 64 x 144
#define OFF_L1   36864           // float4[32]: (w1a0,w1a1,w1b0,w1b1) per pair
#define OFF_B1P  37376           // float2[32]: (b1_0, b1_1)
#define OFF_PA   37632           // float4[32]: (b2_0,b2_1, rs_0,rs_1)
#define OFF_PW   38144           // float4[32]: (w3x0,w3x1, w3y0,w3y1)
#define OFF_RS   38656           // float[64] scratch
#define OFF_ADJ  38912           // float2: (b30 - sum w3x, b31 - sum w3y)
#define SMEM_TOTAL 39040

__device__ __forceinline__ uint32_t smem_u32(const void* p){
    uint32_t a;
    asm("{ .reg .u64 t; cvta.to.shared.u64 t, %1; cvt.u32.u64 %0, t; }" : "=r"(a) : "l"(p));
    return a;
}
__device__ __forceinline__ void ldm_x4(uint32_t* r, uint32_t addr){
    asm volatile("ldmatrix.sync.aligned.m8n8.x4.shared.b16 {%0,%1,%2,%3}, [%4];"
        : "=r"(r[0]),"=r"(r[1]),"=r"(r[2]),"=r"(r[3]) : "r"(addr));
}
__device__ __forceinline__ void mma_f16(float* d, const uint32_t* a, const uint32_t* b){
    asm volatile("mma.sync.aligned.m16n8k16.row.col.f32.f16.f16.f32 "
        "{%0,%1,%2,%3}, {%4,%5,%6,%7}, {%8,%9}, {%0,%1,%2,%3};"
        : "+f"(d[0]),"+f"(d[1]),"+f"(d[2]),"+f"(d[3])
        : "r"(a[0]),"r"(a[1]),"r"(a[2]),"r"(a[3]), "r"(b[0]),"r"(b[1]));
}
__device__ __forceinline__ ull pack2(float a, float b){
    ull v; asm("mov.b64 %0, {%1, %2};" : "=l"(v) : "f"(a), "f"(b)); return v;
}
__device__ __forceinline__ void unpack2(ull v, float &a, float &b){
    asm("mov.b64 {%0, %1}, %2;" : "=f"(a), "=f"(b) : "l"(v));
}
__device__ __forceinline__ void fma2(ull &d, ull a, ull b){
    asm("fma.rn.f32x2 %0, %1, %2, %0;" : "+l"(d) : "l"(a), "l"(b));
}
__device__ __forceinline__ float ex2(float x){
    float r; asm("ex2.approx.f32 %0, %1;" : "=f"(r) : "f"(x)); return r;
}
__device__ __forceinline__ uint32_t packh2(float a, float b){
    __half2 v = __floats2half2_rn(a, b);
    return *reinterpret_cast<uint32_t*>(&v);
}
__device__ __forceinline__ uint32_t hmin0(uint32_t v){
    __half2 a = *reinterpret_cast<__half2*>(&v);
    __half2 z = __floats2half2_rn(0.f, 0.f);
    __half2 m = __hmin2(a, z);
    return *reinterpret_cast<uint32_t*>(&m);
}

__global__ __launch_bounds__(NT, 3)
void odefunc_mma(const float* __restrict__ zlp,
                 const float* __restrict__ W1, const float* __restrict__ b1,
                 const float* __restrict__ W2, const float* __restrict__ b2,
                 const float* __restrict__ W3, const float* __restrict__ b3,
                 float* __restrict__ out, int B, int ntiles)
{
    extern __shared__ char sm[];
    const uint32_t smb = smem_u32(sm);
    const int tid = threadIdx.x, w = tid >> 5, lane = tid & 31;

    float4* sPA = (float4*)(sm + OFF_PA);
    float4* sPW = (float4*)(sm + OFF_PW);
    float*  sRS = (float*)(sm + OFF_RS);

    // ---------- per-CTA weight prep ----------
    // layer-1 tables, pair-packed
    for (int m = tid; m < 32; m += NT){
        *(float4*)(sm + OFF_L1 + m*16) = make_float4(W1[4*m], W1[4*m+2], W1[4*m+1], W1[4*m+3]);
        *(float2*)(sm + OFF_B1P + m*8) = make_float2(b1[2*m], b1[2*m+1]);
    }
    // W2 and trace-matrix planes (fp16)
    for (int idx = tid; idx < H*H; idx += NT){
        int n = idx >> 6, j = idx & 63;
        float w2 = W2[idx];
        float c  = fmaf(W1[2*j], W3[n], W1[2*j+1] * W3[H + n]);   // C[j][n]
        uint32_t off = (uint32_t)(n*RS + 2*j);
        *(__half*)(sm + OFF_W2H + off) = __float2half_rn(w2);
        *(__half*)(sm + OFF_MH  + off) = __float2half_rn(w2 * c);
    }
    if (tid < H){                        // rowsum of exact fp32 M
        float s = 0.f;
        #pragma unroll 8
        for (int j = 0; j < H; j++){
            float c = fmaf(W1[2*j], W3[tid], W1[2*j+1] * W3[H + tid]);
            s += W2[tid*H + j] * c;
        }
        sRS[tid] = s;
    }
    __syncthreads();
    if (tid < 32){
        sPA[tid] = make_float4(b2[2*tid], b2[2*tid+1], sRS[2*tid], sRS[2*tid+1]);
        sPW[tid] = make_float4(W3[2*tid], W3[2*tid+1], W3[H+2*tid], W3[H+2*tid+1]);
    }
    if (tid == 0){                       // fold the epilogue "-1" into the bias
        float sx = 0.f, sy = 0.f;
        #pragma unroll 8
        for (int k = 0; k < H; k++){ sx += W3[k]; sy += W3[H+k]; }
        *(float2*)(sm + OFF_ADJ) = make_float2(b3[0] - sx, b3[1] - sy);
    }
    __syncthreads();

    const float2 adj = *(const float2*)(sm + OFF_ADJ);

    // ldmatrix lane address components
    const int aRow  = (lane & 7) + ((lane >> 3) & 1) * 8;
    const int aColB = (lane >> 4) * 16;
    const int bRow4 = (lane & 7) + ((lane >> 4) & 1) * 8;
    const int bCol4 = ((lane >> 3) & 1) * 16;

    const uint32_t aAH = smb + OFF_AH + (uint32_t)((w*32 + aRow)*RS + aColB);
    const uint32_t bW2 = smb + OFF_W2H + (uint32_t)(bRow4*RS + bCol4);
    const uint32_t bM  = smb + OFF_MH  + (uint32_t)(bRow4*RS + bCol4);

    for (int tile = blockIdx.x; tile < ntiles; tile += gridDim.x){
        const int base = tile * TILE;
        const int s = base + tid;
        const bool ok = (s < B);
        float z0 = 0.f, z1 = 0.f;
        if (ok){ z0 = zlp[3*s]; z1 = zlp[3*s + 1]; }
        const ull z0p = pack2(z0, z0), z1p = pack2(z1, z1);

        // ---- fill this thread's A row: h = elu(W1 z + b1) as fp16 ----
        {
            const uint32_t rbase = (uint32_t)tid * RS;
            #pragma unroll
            for (int jb = 0; jb < 8; jb++){
                uint4 vh;
                uint32_t* ph = (uint32_t*)&vh;
                #pragma unroll
                for (int q = 0; q < 4; q++){
                    int m = jb*4 + q;
                    ulonglong2 Lw = *(const ulonglong2*)(sm + OFF_L1 + m*16);
                    ull a = *(const ull*)(sm + OFF_B1P + m*8);
                    fma2(a, Lw.y, z1p);          // + w1b * z1
                    fma2(a, Lw.x, z0p);          // + w1a * z0
                    float a0, a1; unpack2(a, a0, a1);
                    float e0 = ex2(fminf(a0, 0.f) * L2E);
                    float e1 = ex2(fminf(a1, 0.f) * L2E);
                    float h0 = fmaxf(a0, 0.f) + e0 - 1.f;
                    float h1 = fmaxf(a1, 0.f) + e1 - 1.f;
                    ph[q] = packh2(ok ? h0 : 0.f, ok ? h1 : 0.f);
                }
                *(uint4*)(sm + OFF_AH + rbase + jb*16) = vh;
            }
        }
        __syncwarp();

        float o0[2][2] = {{0,0},{0,0}}, o1[2][2] = {{0,0},{0,0}}, tr[2][2] = {{0,0},{0,0}};

        // ---- warp-local GEMM: half outer, B fragments shared across both m-tiles ----
        #pragma unroll
        for (int half = 0; half < 2; half++){
            float dv[2][4][4], dt[2][4][4];
            #pragma unroll
            for (int mt = 0; mt < 2; mt++)
                #pragma unroll
                for (int ng = 0; ng < 4; ng++)
                    #pragma unroll
                    for (int e = 0; e < 4; e++){ dv[mt][ng][e] = 0.f; dt[mt][ng][e] = 0.f; }

            #pragma unroll
            for (int kc = 0; kc < 4; kc++){
                uint32_t roff0 = (uint32_t)((half*32     )*RS + kc*32);
                uint32_t roff1 = (uint32_t)((half*32 + 16)*RS + kc*32);
                uint32_t bv[8], bm[8];
                ldm_x4(bv,     bW2 + roff0);
                ldm_x4(bv + 4, bW2 + roff1);
                ldm_x4(bm,     bM  + roff0);
                ldm_x4(bm + 4, bM  + roff1);
                #pragma unroll
                for (int mt = 0; mt < 2; mt++){
                    uint32_t ah[4], nh[4];
                    ldm_x4(ah, aAH + (uint32_t)(mt*16*RS + kc*32));
                    #pragma unroll
                    for (int e = 0; e < 4; e++) nh[e] = hmin0(ah[e]);
                    #pragma unroll
                    for (int ng = 0; ng < 4; ng++){
                        mma_f16(dv[mt][ng], ah, bv + 2*ng);
                        mma_f16(dt[mt][ng], nh, bm + 2*ng);
                    }
                }
            }

            // ---- epilogue: g2 = exp(min(a,0)); h' = max(a,0)+exp(min(a,0)) ----
            #pragma unroll
            for (int ng = 0; ng < 4; ng++){
                int m = half*16 + ng*4 + (lane & 3);
                float4 pa = sPA[m];   // (b2_0, b2_1, rs_0, rs_1)
                float4 pw = sPW[m];   // (w3x0, w3x1, w3y0, w3y1)
                #pragma unroll
                for (int mt = 0; mt < 2; mt++)
                    #pragma unroll
                    for (int rr = 0; rr < 2; rr++){
                        float v0 = dv[mt][ng][2*rr],   td0 = dt[mt][ng][2*rr];
                        float v1 = dv[mt][ng][2*rr+1], td1 = dt[mt][ng][2*rr+1];
                        float a0 = v0 + pa.x, a1 = v1 + pa.y;
                        float e0 = ex2(fminf(a0, 0.f) * L2E);
                        float e1 = ex2(fminf(a1, 0.f) * L2E);
                        float h0 = fmaxf(a0, 0.f) + e0;
                        float h1 = fmaxf(a1, 0.f) + e1;
                        o0[mt][rr] = fmaf(pw.x, h0, fmaf(pw.y, h1, o0[mt][rr]));
                        o1[mt][rr] = fmaf(pw.z, h0, fmaf(pw.w, h1, o1[mt][rr]));
                        tr[mt][rr] = fmaf(e0, td0 + pa.z, fmaf(e1, td1 + pa.w, tr[mt][rr]));
                    }
            }
        }

        // ---- reduce across the 4 lanes of each row group, store ----
        #pragma unroll
        for (int mt = 0; mt < 2; mt++)
            #pragma unroll
            for (int rr = 0; rr < 2; rr++){
                o0[mt][rr] += __shfl_xor_sync(0xffffffffu, o0[mt][rr], 1);
                o0[mt][rr] += __shfl_xor_sync(0xffffffffu, o0[mt][rr], 2);
                o1[mt][rr] += __shfl_xor_sync(0xffffffffu, o1[mt][rr], 1);
                o1[mt][rr] += __shfl_xor_sync(0xffffffffu, o1[mt][rr], 2);
                tr[mt][rr] += __shfl_xor_sync(0xffffffffu, tr[mt][rr], 1);
                tr[mt][rr] += __shfl_xor_sync(0xffffffffu, tr[mt][rr], 2);
            }
        if ((lane & 3) == 0){
            int g = lane >> 2;
            #pragma unroll
            for (int mt = 0; mt < 2; mt++)
                #pragma unroll
                for (int rr = 0; rr < 2; rr++){
                    int s2 = base + w*32 + mt*16 + g + rr*8;
                    if (s2 < B){
                        out[3*s2]     = o0[mt][rr] + adj.x;
                        out[3*s2 + 1] = o1[mt][rr] + adj.y;
                        out[3*s2 + 2] = -tr[mt][rr];
                    }
                }
        }
        __syncwarp();
    }
}

extern "C" void kernel_launch(void* const* d_in, const int* in_sizes, int n_in,
                              void* d_out, int out_size)
{
    // metadata order: t, z_and_logp, W1, b1, W2, b2, W3, b3
    const float* zlp = (const float*)d_in[1];
    const float* W1  = (const float*)d_in[2];
    const float* b1  = (const float*)d_in[3];
    const float* W2  = (const float*)d_in[4];
    const float* b2  = (const float*)d_in[5];
    const float* W3  = (const float*)d_in[6];
    const float* b3  = (const float*)d_in[7];
    float* out = (float*)d_out;
    int B = in_sizes[1] / 3;
    int ntiles = (B + TILE - 1) / TILE;

    cudaFuncSetAttribute(odefunc_mma, cudaFuncAttributeMaxDynamicSharedMemorySize, SMEM_TOTAL);
    int grid = 444;               // 3 CTAs x 148 SMs, persistent
    if (grid > ntiles) grid = ntiles;
    odefunc_mma<<<grid, NT, SMEM_TOTAL>>>(zlp, W1, b1, W2, b2, W3, b3, out, B, ntiles);
}

// round 13
// speedup vs baseline: 1.4121x; 1.4121x over previous
#include <cuda_runtime.h>
#include <cuda_fp16.h>
#include <cstdint>

#define H 64
#define TILE 256
#define NT 256
#define RS 144                  // smem row stride (bytes): 9*16 -> conflict-free ldmatrix
#define L2E 1.4426950408889634f

// ---- smem layout (bytes) ----
#define OFF_AH   0               // h (fp16)        : 256 x 144 = 36864
#define OFF_W2H  36864           // W2 (fp16)       : 64 x 144
#define OFF_MH   46080           // M  (fp16)       : 64 x 144
#define OFF_TBL  55296           // float4[64]: (b2, rsM, W3_0, W3_1)
#define OFF_W1A  56320           // float[64]
#define OFF_W1B  56576
#define OFF_B1   56832
#define OFF_ADJ  57088           // float2: (b3_0 - sum W3_0, b3_1 - sum W3_1)
#define SMEM_TOTAL 57344

__device__ __forceinline__ uint32_t smem_u32(const void* p){
    uint32_t a;
    asm("{ .reg .u64 t; cvta.to.shared.u64 t, %1; cvt.u32.u64 %0, t; }" : "=r"(a) : "l"(p));
    return a;
}
__device__ __forceinline__ void ldm_x4(uint32_t* r, uint32_t addr){
    asm volatile("ldmatrix.sync.aligned.m8n8.x4.shared.b16 {%0,%1,%2,%3}, [%4];"
        : "=r"(r[0]),"=r"(r[1]),"=r"(r[2]),"=r"(r[3]) : "r"(addr));
}
__device__ __forceinline__ void mma_f16(float* d, const uint32_t* a, const uint32_t* b){
    asm volatile("mma.sync.aligned.m16n8k16.row.col.f32.f16.f16.f32 "
        "{%0,%1,%2,%3}, {%4,%5,%6,%7}, {%8,%9}, {%0,%1,%2,%3};"
        : "+f"(d[0]),"+f"(d[1]),"+f"(d[2]),"+f"(d[3])
        : "r"(a[0]),"r"(a[1]),"r"(a[2]),"r"(a[3]), "r"(b[0]),"r"(b[1]));
}
__device__ __forceinline__ float elu(float x){ return x > 0.f ? x : (__expf(x) - 1.f); }
__device__ __forceinline__ float ex2(float x){
    float r; asm("ex2.approx.f32 %0, %1;" : "=f"(r) : "f"(x)); return r;
}
__device__ __forceinline__ uint32_t packh2(float a, float b){
    __half2 v = __floats2half2_rn(a, b);
    return *reinterpret_cast<uint32_t*>(&v);
}
// elementwise min(x, 0) on packed fp16
__device__ __forceinline__ uint32_t hmin0(uint32_t v){
    __half2 a = *reinterpret_cast<__half2*>(&v);
    __half2 z = __floats2half2_rn(0.f, 0.f);
    __half2 m = __hmin2(a, z);
    return *reinterpret_cast<uint32_t*>(&m);
}

__global__ __launch_bounds__(NT, 2)
void odefunc_mma(const float* __restrict__ zlp,
                 const float* __restrict__ W1, const float* __restrict__ b1,
                 const float* __restrict__ W2, const float* __restrict__ b2,
                 const float* __restrict__ W3, const float* __restrict__ b3,
                 float* __restrict__ out, int B, int ntiles)
{
    extern __shared__ char sm[];
    const uint32_t smb = smem_u32(sm);
    const int tid = threadIdx.x, w = tid >> 5, lane = tid & 31;

    float*  sW1a = (float*)(sm + OFF_W1A);
    float*  sW1b = (float*)(sm + OFF_W1B);
    float*  sB1  = (float*)(sm + OFF_B1);
    float4* sTBL = (float4*)(sm + OFF_TBL);

    // ---------- per-CTA weight prep ----------
    for (int j = tid; j < H; j += NT){
        sW1a[j] = W1[2*j]; sW1b[j] = W1[2*j+1]; sB1[j] = b1[j];
    }

    for (int idx = tid; idx < H*H; idx += NT){
        int n = idx >> 6, j = idx & 63;            // n = output neuron, j = input
        float w2 = W2[idx];
        float c  = fmaf(W1[2*j], W3[n], W1[2*j+1] * W3[H + n]);   // C[j][n]
        uint32_t off = (uint32_t)(n*RS + 2*j);
        *(__half*)(sm + OFF_W2H + off) = __float2half_rn(w2);
        *(__half*)(sm + OFF_MH  + off) = __float2half_rn(w2 * c);
    }
    if (tid < H){
        float s = 0.f;
        #pragma unroll 8
        for (int j = 0; j < H; j++){
            float c = fmaf(W1[2*j], W3[tid], W1[2*j+1] * W3[H + tid]);
            s += W2[tid*H + j] * c;
        }
        sTBL[tid] = make_float4(b2[tid], s, W3[tid], W3[H + tid]);
    }
    if (tid == 0){                       // fold the epilogue "-1" into the output bias
        float sx = 0.f, sy = 0.f;
        #pragma unroll 8
        for (int k = 0; k < H; k++){ sx += W3[k]; sy += W3[H + k]; }
        *(float2*)(sm + OFF_ADJ) = make_float2(b3[0] - sx, b3[1] - sy);
    }
    __syncthreads();

    const float2 adj = *(const float2*)(sm + OFF_ADJ);

    // ldmatrix lane address components
    const int aRow  = (lane & 7) + ((lane >> 3) & 1) * 8;     // A x4: rows within 16
    const int aColB = (lane >> 4) * 16;
    const int bRow4 = (lane & 7) + ((lane >> 4) & 1) * 8;     // B x4: n within ng-pair
    const int bCol4 = ((lane >> 3) & 1) * 16;

    const uint32_t aAH  = smb + OFF_AH + (uint32_t)((w*32 + aRow)*RS + aColB);
    const uint32_t bW2  = smb + OFF_W2H + (uint32_t)(bRow4*RS + bCol4);
    const uint32_t bM   = smb + OFF_MH  + (uint32_t)(bRow4*RS + bCol4);

    for (int tile = blockIdx.x; tile < ntiles; tile += gridDim.x){
        const int base = tile * TILE;
        const int s = base + tid;
        const bool ok = (s < B);
        float z0 = 0.f, z1 = 0.f;
        if (ok){ z0 = zlp[3*s]; z1 = zlp[3*s + 1]; }

        // ---- fill this thread's A row: h as fp16, 16B chunks ----
        {
            const uint32_t rbase = (uint32_t)tid * RS;
            #pragma unroll
            for (int jb = 0; jb < 8; jb++){
                uint4 vh;
                uint32_t* ph = (uint32_t*)&vh;
                #pragma unroll
                for (int q = 0; q < 4; q++){
                    int j = jb*8 + 2*q;
                    float a0 = fmaf(sW1a[j],   z0, fmaf(sW1b[j],   z1, sB1[j]));
                    float a1 = fmaf(sW1a[j+1], z0, fmaf(sW1b[j+1], z1, sB1[j+1]));
                    float h0 = ok ? elu(a0) : 0.f;
                    float h1 = ok ? elu(a1) : 0.f;
                    ph[q] = packh2(h0, h1);
                }
                *(uint4*)(sm + OFF_AH + rbase + jb*16) = vh;
            }
        }
        __syncwarp();

        // ---- warp-local GEMM: mt outer; B fragments loaded JIT from smem ----
        #pragma unroll
        for (int mt = 0; mt < 2; mt++){
            // A fragments for this m-tile, all kc (16 regs)
            uint32_t ah[4][4];
            #pragma unroll
            for (int kc = 0; kc < 4; kc++)
                ldm_x4(ah[kc], aAH + (uint32_t)(mt*16*RS + kc*32));

            float o0[2] = {0.f, 0.f}, o1[2] = {0.f, 0.f}, tr[2] = {0.f, 0.f};

            #pragma unroll
            for (int half = 0; half < 2; half++){
                float dv[4][4], dt[4][4];
                #pragma unroll
                for (int ng = 0; ng < 4; ng++)
                    #pragma unroll
                    for (int e = 0; e < 4; e++){ dv[ng][e] = 0.f; dt[ng][e] = 0.f; }

                #pragma unroll
                for (int kc = 0; kc < 4; kc++){
                    uint32_t roff0 = (uint32_t)((half*32     )*RS + kc*32);
                    uint32_t roff1 = (uint32_t)((half*32 + 16)*RS + kc*32);
                    uint32_t bv[8], bm[8];
                    ldm_x4(bv,     bW2 + roff0);
                    ldm_x4(bv + 4, bW2 + roff1);
                    ldm_x4(bm,     bM  + roff0);
                    ldm_x4(bm + 4, bM  + roff1);
                    uint32_t nh[4];
                    #pragma unroll
                    for (int e = 0; e < 4; e++) nh[e] = hmin0(ah[kc][e]);
                    #pragma unroll
                    for (int ng = 0; ng < 4; ng++){
                        mma_f16(dv[ng], ah[kc], bv + 2*ng);
                        mma_f16(dt[ng], nh,     bm + 2*ng);
                    }
                }

                // ---- epilogue: e = exp(min(a,0)) = elu'(a); h' = max(a,0)+e ----
                #pragma unroll
                for (int ng = 0; ng < 4; ng++){
                    int n0 = half*32 + ng*8 + 2*(lane & 3);
                    float4 t0 = sTBL[n0], t1 = sTBL[n0 + 1];
                    #pragma unroll
                    for (int rr = 0; rr < 2; rr++){
                        float v0 = dv[ng][2*rr],     tv0 = dt[ng][2*rr];
                        float v1 = dv[ng][2*rr + 1], tv1 = dt[ng][2*rr + 1];
                        float a0 = v0 + t0.x;
                        float a1 = v1 + t1.x;
                        float e0 = ex2(fminf(a0, 0.f) * L2E);
                        float e1 = ex2(fminf(a1, 0.f) * L2E);
                        float h0 = fmaxf(a0, 0.f) + e0;     // = elu(a)+1
                        float h1 = fmaxf(a1, 0.f) + e1;
                        o0[rr] = fmaf(t0.z, h0, fmaf(t1.z, h1, o0[rr]));
                        o1[rr] = fmaf(t0.w, h0, fmaf(t1.w, h1, o1[rr]));
                        tr[rr] = fmaf(e0, tv0 + t0.y, fmaf(e1, tv1 + t1.y, tr[rr]));
                    }
                }
            }

            // ---- reduce across the 4 lanes of each row group, store (per mt) ----
            #pragma unroll
            for (int rr = 0; rr < 2; rr++){
                o0[rr] += __shfl_xor_sync(0xffffffffu, o0[rr], 1);
                o0[rr] += __shfl_xor_sync(0xffffffffu, o0[rr], 2);
                o1[rr] += __shfl_xor_sync(0xffffffffu, o1[rr], 1);
                o1[rr] += __shfl_xor_sync(0xffffffffu, o1[rr], 2);
                tr[rr] += __shfl_xor_sync(0xffffffffu, tr[rr], 1);
                tr[rr] += __shfl_xor_sync(0xffffffffu, tr[rr], 2);
            }
            if ((lane & 3) == 0){
                int g = lane >> 2;
                #pragma unroll
                for (int rr = 0; rr < 2; rr++){
                    int s2 = base + w*32 + mt*16 + g + rr*8;
                    if (s2 < B){
                        out[3*s2]     = o0[rr] + adj.x;
                        out[3*s2 + 1] = o1[rr] + adj.y;
                        out[3*s2 + 2] = -tr[rr];
                    }
                }
            }
        }
        __syncwarp();
    }
}

extern "C" void kernel_launch(void* const* d_in, const int* in_sizes, int n_in,
                              void* d_out, int out_size)
{
    // metadata order: t, z_and_logp, W1, b1, W2, b2, W3, b3
    const float* zlp = (const float*)d_in[1];
    const float* W1  = (const float*)d_in[2];
    const float* b1  = (const float*)d_in[3];
    const float* W2  = (const float*)d_in[4];
    const float* b2  = (const float*)d_in[5];
    const float* W3  = (const float*)d_in[6];
    const float* b3  = (const float*)d_in[7];
    float* out = (float*)d_out;
    int B = in_sizes[1] / 3;
    int ntiles = (B + TILE - 1) / TILE;

    cudaFuncSetAttribute(odefunc_mma, cudaFuncAttributeMaxDynamicSharedMemorySize, SMEM_TOTAL);
    int grid = 296;               // 2 CTAs x 148 SMs, persistent
    if (grid > ntiles) grid = ntiles;
    odefunc_mma<<<grid, NT, SMEM_TOTAL>>>(zlp, W1, b1, W2, b2, W3, b3, out, B, ntiles);
}

// round 14
// speedup vs baseline: 1.5586x; 1.1038x over previous
#include <cuda_runtime.h>
#include <cuda_fp16.h>
#include <cstdint>

#define H 64
#define TILE 256
#define NT 256
#define RS 144                  // smem row stride (bytes): 9*16 -> conflict-free ldmatrix
#define L2E 1.4426950408889634f

typedef unsigned long long ull;

// ---- smem layout (bytes) ----
#define OFF_AH   0               // h+1 (fp16)      : 256 x 144 = 36864
#define OFF_W2H  36864           // W2 (fp16)       : 64 x 144
#define OFF_MH   46080           // M  (fp16)       : 64 x 144
#define OFF_TBL  55296           // float4[64]: (b2 - rowsumW2, unused, W3_0, W3_1)
#define OFF_L1   56320           // float4[32]: (w1a_0, w1a_1, w1b_0, w1b_1) per pair
#define OFF_B1P  56832           // float2[32]
#define OFF_ADJ  57088           // float2: (b3_0 - sum W3_0, b3_1 - sum W3_1)
#define OFF_RSW  57096           // float[64] scratch (rowsum W2)
#define SMEM_TOTAL 57600

__device__ __forceinline__ uint32_t smem_u32(const void* p){
    uint32_t a;
    asm("{ .reg .u64 t; cvta.to.shared.u64 t, %1; cvt.u32.u64 %0, t; }" : "=r"(a) : "l"(p));
    return a;
}
__device__ __forceinline__ void ldm_x4(uint32_t* r, uint32_t addr){
    asm volatile("ldmatrix.sync.aligned.m8n8.x4.shared.b16 {%0,%1,%2,%3}, [%4];"
        : "=r"(r[0]),"=r"(r[1]),"=r"(r[2]),"=r"(r[3]) : "r"(addr));
}
__device__ __forceinline__ void mma_f16(float* d, const uint32_t* a, const uint32_t* b){
    asm volatile("mma.sync.aligned.m16n8k16.row.col.f32.f16.f16.f32 "
        "{%0,%1,%2,%3}, {%4,%5,%6,%7}, {%8,%9}, {%0,%1,%2,%3};"
        : "+f"(d[0]),"+f"(d[1]),"+f"(d[2]),"+f"(d[3])
        : "r"(a[0]),"r"(a[1]),"r"(a[2]),"r"(a[3]), "r"(b[0]),"r"(b[1]));
}
__device__ __forceinline__ ull pack2(float a, float b){
    ull v; asm("mov.b64 %0, {%1, %2};" : "=l"(v) : "f"(a), "f"(b)); return v;
}
__device__ __forceinline__ void unpack2(ull v, float &a, float &b){
    asm("mov.b64 {%0, %1}, %2;" : "=f"(a), "=f"(b) : "l"(v));
}
__device__ __forceinline__ void fma2(ull &d, ull a, ull b){
    asm("fma.rn.f32x2 %0, %1, %2, %0;" : "+l"(d) : "l"(a), "l"(b));
}
__device__ __forceinline__ float ex2(float x){
    float r; asm("ex2.approx.f32 %0, %1;" : "=f"(r) : "f"(x)); return r;
}
__device__ __forceinline__ uint32_t packh2(float a, float b){
    __half2 v = __floats2half2_rn(a, b);
    return *reinterpret_cast<uint32_t*>(&v);
}
// elementwise min(x, 1) on packed fp16: min(h',1) = min(h,0)+1
__device__ __forceinline__ uint32_t hmin1(uint32_t v){
    __half2 a = *reinterpret_cast<__half2*>(&v);
    __half2 one = __floats2half2_rn(1.f, 1.f);
    __half2 m = __hmin2(a, one);
    return *reinterpret_cast<uint32_t*>(&m);
}

__global__ __launch_bounds__(NT, 2)
void odefunc_mma(const float* __restrict__ zlp,
                 const float* __restrict__ W1, const float* __restrict__ b1,
                 const float* __restrict__ W2, const float* __restrict__ b2,
                 const float* __restrict__ W3, const float* __restrict__ b3,
                 float* __restrict__ out, int B, int ntiles)
{
    extern __shared__ char sm[];
    const uint32_t smb = smem_u32(sm);
    const int tid = threadIdx.x, w = tid >> 5, lane = tid & 31;

    float4* sTBL = (float4*)(sm + OFF_TBL);
    float*  sRSW = (float*)(sm + OFF_RSW);

    // ---------- per-CTA weight prep ----------
    for (int m = tid; m < 32; m += NT){
        *(float4*)(sm + OFF_L1 + m*16) = make_float4(W1[4*m], W1[4*m+2], W1[4*m+1], W1[4*m+3]);
        *(float2*)(sm + OFF_B1P + m*8) = make_float2(b1[2*m], b1[2*m+1]);
    }

    for (int idx = tid; idx < H*H; idx += NT){
        int n = idx >> 6, j = idx & 63;            // n = output neuron, j = input
        float w2 = W2[idx];
        float c  = fmaf(W1[2*j], W3[n], W1[2*j+1] * W3[H + n]);   // C[j][n]
        uint32_t off = (uint32_t)(n*RS + 2*j);
        *(__half*)(sm + OFF_W2H + off) = __float2half_rn(w2);
        *(__half*)(sm + OFF_MH  + off) = __float2half_rn(w2 * c);
    }
    if (tid < H){
        float s = 0.f;                             // rowsum of W2 (exact fp32)
        #pragma unroll 8
        for (int j = 0; j < H; j++) s += W2[tid*H + j];
        sRSW[tid] = s;
    }
    __syncthreads();
    if (tid < H){
        // a2 = W2*h + b2 = W2*h' + (b2 - rowsumW2);  t = M*min(h',1)  (rs folds away)
        sTBL[tid] = make_float4(b2[tid] - sRSW[tid], 0.f, W3[tid], W3[H + tid]);
    }
    if (tid == 0){                       // fold the epilogue "-1" of h2 into the output bias
        float sx = 0.f, sy = 0.f;
        #pragma unroll 8
        for (int k = 0; k < H; k++){ sx += W3[k]; sy += W3[H + k]; }
        *(float2*)(sm + OFF_ADJ) = make_float2(b3[0] - sx, b3[1] - sy);
    }
    __syncthreads();

    const float2 adj = *(const float2*)(sm + OFF_ADJ);

    // ldmatrix lane address components
    const int aRow  = (lane & 7) + ((lane >> 3) & 1) * 8;     // A x4: rows within 16
    const int aColB = (lane >> 4) * 16;
    const int bRow4 = (lane & 7) + ((lane >> 4) & 1) * 8;     // B x4: n within ng-pair
    const int bCol4 = ((lane >> 3) & 1) * 16;

    const uint32_t aAH  = smb + OFF_AH + (uint32_t)((w*32 + aRow)*RS + aColB);
    const uint32_t bW2  = smb + OFF_W2H + (uint32_t)(bRow4*RS + bCol4);
    const uint32_t bM   = smb + OFF_MH  + (uint32_t)(bRow4*RS + bCol4);

    for (int tile = blockIdx.x; tile < ntiles; tile += gridDim.x){
        const int base = tile * TILE;
        const int s = base + tid;
        const bool ok = (s < B);
        float z0 = 0.f, z1 = 0.f;
        if (ok){ z0 = zlp[3*s]; z1 = zlp[3*s + 1]; }
        const ull z0p = pack2(z0, z0), z1p = pack2(z1, z1);

        // ---- fill this thread's A row: h' = h+1 = max(a,0)+exp(min(a,0)), fp16 ----
        {
            const uint32_t rbase = (uint32_t)tid * RS;
            #pragma unroll
            for (int jb = 0; jb < 8; jb++){
                uint4 vh;
                uint32_t* ph = (uint32_t*)&vh;
                #pragma unroll
                for (int q = 0; q < 4; q++){
                    int m = jb*4 + q;
                    ulonglong2 Lw = *(const ulonglong2*)(sm + OFF_L1 + m*16);
                    ull a = *(const ull*)(sm + OFF_B1P + m*8);
                    fma2(a, Lw.y, z1p);              // + w1b * z1
                    fma2(a, Lw.x, z0p);              // + w1a * z0
                    float a0, a1; unpack2(a, a0, a1);
                    float h0 = fmaxf(a0, 0.f) + ex2(fminf(a0, 0.f) * L2E);
                    float h1 = fmaxf(a1, 0.f) + ex2(fminf(a1, 0.f) * L2E);
                    ph[q] = ok ? packh2(h0, h1) : 0u;
                }
                *(uint4*)(sm + OFF_AH + rbase + jb*16) = vh;
            }
        }
        __syncwarp();

        // ---- warp-local GEMM: mt outer; B fragments loaded JIT from smem ----
        #pragma unroll
        for (int mt = 0; mt < 2; mt++){
            // A fragments for this m-tile, all kc (16 regs)
            uint32_t ah[4][4];
            #pragma unroll
            for (int kc = 0; kc < 4; kc++)
                ldm_x4(ah[kc], aAH + (uint32_t)(mt*16*RS + kc*32));

            float o0[2] = {0.f, 0.f}, o1[2] = {0.f, 0.f}, tr[2] = {0.f, 0.f};

            #pragma unroll
            for (int half = 0; half < 2; half++){
                float dv[4][4], dt[4][4];
                #pragma unroll
                for (int ng = 0; ng < 4; ng++)
                    #pragma unroll
                    for (int e = 0; e < 4; e++){ dv[ng][e] = 0.f; dt[ng][e] = 0.f; }

                #pragma unroll
                for (int kc = 0; kc < 4; kc++){
                    uint32_t roff0 = (uint32_t)((half*32     )*RS + kc*32);
                    uint32_t roff1 = (uint32_t)((half*32 + 16)*RS + kc*32);
                    uint32_t bv[8], bm[8];
                    ldm_x4(bv,     bW2 + roff0);
                    ldm_x4(bv + 4, bW2 + roff1);
                    ldm_x4(bm,     bM  + roff0);
                    ldm_x4(bm + 4, bM  + roff1);
                    uint32_t nh[4];
                    #pragma unroll
                    for (int e = 0; e < 4; e++) nh[e] = hmin1(ah[kc][e]);
                    #pragma unroll
                    for (int ng = 0; ng < 4; ng++){
                        mma_f16(dv[ng], ah[kc], bv + 2*ng);   // W2 * h'
                        mma_f16(dt[ng], nh,     bm + 2*ng);   // M * min(h',1) = t_k
                    }
                }

                // ---- epilogue: a2 = dv + (b2-rsW2); e = elu'(a2); h2' = max+e ----
                #pragma unroll
                for (int ng = 0; ng < 4; ng++){
                    int n0 = half*32 + ng*8 + 2*(lane & 3);
                    float4 t0 = sTBL[n0], t1 = sTBL[n0 + 1];
                    #pragma unroll
                    for (int rr = 0; rr < 2; rr++){
                        float v0 = dv[ng][2*rr],     tv0 = dt[ng][2*rr];
                        float v1 = dv[ng][2*rr + 1], tv1 = dt[ng][2*rr + 1];
                        float a0 = v0 + t0.x;
                        float a1 = v1 + t1.x;
                        float e0 = ex2(fminf(a0, 0.f) * L2E);
                        float e1 = ex2(fminf(a1, 0.f) * L2E);
                        float h0 = fmaxf(a0, 0.f) + e0;     // = elu(a)+1
                        float h1 = fmaxf(a1, 0.f) + e1;
                        o0[rr] = fmaf(t0.z, h0, fmaf(t1.z, h1, o0[rr]));
                        o1[rr] = fmaf(t0.w, h0, fmaf(t1.w, h1, o1[rr]));
                        tr[rr] = fmaf(e0, tv0, fmaf(e1, tv1, tr[rr]));
                    }
                }
            }

            // ---- reduce across the 4 lanes of each row group, store (per mt) ----
            #pragma unroll
            for (int rr = 0; rr < 2; rr++){
                o0[rr] += __shfl_xor_sync(0xffffffffu, o0[rr], 1);
                o0[rr] += __shfl_xor_sync(0xffffffffu, o0[rr], 2);
                o1[rr] += __shfl_xor_sync(0xffffffffu, o1[rr], 1);
                o1[rr] += __shfl_xor_sync(0xffffffffu, o1[rr], 2);
                tr[rr] += __shfl_xor_sync(0xffffffffu, tr[rr], 1);
                tr[rr] += __shfl_xor_sync(0xffffffffu, tr[rr], 2);
            }
            if ((lane & 3) == 0){
                int g = lane >> 2;
                #pragma unroll
                for (int rr = 0; rr < 2; rr++){
                    int s2 = base + w*32 + mt*16 + g + rr*8;
                    if (s2 < B){
                        out[3*s2]     = o0[rr] + adj.x;
                        out[3*s2 + 1] = o1[rr] + adj.y;
                        out[3*s2 + 2] = -tr[rr];
                    }
                }
            }
        }
        __syncwarp();
    }
}

extern "C" void kernel_launch(void* const* d_in, const int* in_sizes, int n_in,
                              void* d_out, int out_size)
{
    // metadata order: t, z_and_logp, W1, b1, W2, b2, W3, b3
    const float* zlp = (const float*)d_in[1];
    const float* W1  = (const float*)d_in[2];
    const float* b1  = (const float*)d_in[3];
    const float* W2  = (const float*)d_in[4];
    const float* b2  = (const float*)d_in[5];
    const float* W3  = (const float*)d_in[6];
    const float* b3  = (const float*)d_in[7];
    float* out = (float*)d_out;
    int B = in_sizes[1] / 3;
    int ntiles = (B + TILE - 1) / TILE;

    cudaFuncSetAttribute(odefunc_mma, cudaFuncAttributeMaxDynamicSharedMemorySize, SMEM_TOTAL);
    int grid = 296;               // 2 CTAs x 148 SMs, persistent
    if (grid > ntiles) grid = ntiles;
    odefunc_mma<<<grid, NT, SMEM_TOTAL>>>(zlp, W1, b1, W2, b2, W3, b3, out, B, ntiles);
}

// round 15
// speedup vs baseline: 1.5655x; 1.0044x over previous
#include <cuda_runtime.h>
#include <cuda_fp16.h>
#include <cstdint>

#define H 64
#define TILE 256
#define NT 256
#define RS 144                  // smem row stride (bytes): 9*16 -> conflict-free ldmatrix
#define L2E 1.4426950408889634f

typedef unsigned long long ull;

// ---- smem layout (bytes) ----
#define OFF_AH   0               // h+1 (fp16)      : 256 x 144 = 36864
#define OFF_W2H  36864           // W2 (fp16)       : 64 x 144
#define OFF_MH   46080           // M  (fp16)       : 64 x 144
#define OFF_TBL  55296           // float4[64]: (b2 - rowsumW2, unused, W3_0, W3_1)
#define OFF_L1   56320           // float4[32]: (w1a_0, w1a_1, w1b_0, w1b_1) per pair
#define OFF_B1P  56832           // float2[32]
#define OFF_ADJ  57088           // float2: (b3_0 - sum W3_0, b3_1 - sum W3_1)
#define OFF_RSW  57096           // float[64] scratch (rowsum W2)
#define SMEM_TOTAL 57600

__device__ __forceinline__ uint32_t smem_u32(const void* p){
    uint32_t a;
    asm("{ .reg .u64 t; cvta.to.shared.u64 t, %1; cvt.u32.u64 %0, t; }" : "=r"(a) : "l"(p));
    return a;
}
__device__ __forceinline__ void ldm_x4(uint32_t* r, uint32_t addr){
    asm volatile("ldmatrix.sync.aligned.m8n8.x4.shared.b16 {%0,%1,%2,%3}, [%4];"
        : "=r"(r[0]),"=r"(r[1]),"=r"(r[2]),"=r"(r[3]) : "r"(addr));
}
__device__ __forceinline__ void mma_f16(float* d, const uint32_t* a, const uint32_t* b){
    asm volatile("mma.sync.aligned.m16n8k16.row.col.f32.f16.f16.f32 "
        "{%0,%1,%2,%3}, {%4,%5,%6,%7}, {%8,%9}, {%0,%1,%2,%3};"
        : "+f"(d[0]),"+f"(d[1]),"+f"(d[2]),"+f"(d[3])
        : "r"(a[0]),"r"(a[1]),"r"(a[2]),"r"(a[3]), "r"(b[0]),"r"(b[1]));
}
__device__ __forceinline__ ull pack2(float a, float b){
    ull v; asm("mov.b64 %0, {%1, %2};" : "=l"(v) : "f"(a), "f"(b)); return v;
}
__device__ __forceinline__ void unpack2(ull v, float &a, float &b){
    asm("mov.b64 {%0, %1}, %2;" : "=f"(a), "=f"(b) : "l"(v));
}
__device__ __forceinline__ void fma2(ull &d, ull a, ull b){
    asm("fma.rn.f32x2 %0, %1, %2, %0;" : "+l"(d) : "l"(a), "l"(b));
}
__device__ __forceinline__ float ex2(float x){
    float r; asm("ex2.approx.f32 %0, %1;" : "=f"(r) : "f"(x)); return r;
}
__device__ __forceinline__ uint32_t packh2(float a, float b){
    __half2 v = __floats2half2_rn(a, b);
    return *reinterpret_cast<uint32_t*>(&v);
}
// elementwise min(x, 1) on packed fp16: min(h',1) = min(h,0)+1
__device__ __forceinline__ uint32_t hmin1(uint32_t v){
    __half2 a = *reinterpret_cast<__half2*>(&v);
    __half2 one = __floats2half2_rn(1.f, 1.f);
    __half2 m = __hmin2(a, one);
    return *reinterpret_cast<uint32_t*>(&m);
}

// fill this thread's A row: h' = h+1 = max(a,0)+exp(min(a,0)), fp16
__device__ __forceinline__ void fill_row(char* sm, uint32_t rbase,
                                         ull z0p, ull z1p, bool ok){
    #pragma unroll
    for (int jb = 0; jb < 8; jb++){
        uint4 vh;
        uint32_t* ph = (uint32_t*)&vh;
        #pragma unroll
        for (int q = 0; q < 4; q++){
            int m = jb*4 + q;
            ulonglong2 Lw = *(const ulonglong2*)(sm + OFF_L1 + m*16);
            ull a = *(const ull*)(sm + OFF_B1P + m*8);
            fma2(a, Lw.y, z1p);              // + w1b * z1
            fma2(a, Lw.x, z0p);              // + w1a * z0
            float a0, a1; unpack2(a, a0, a1);
            float h0 = fmaxf(a0, 0.f) + ex2(fminf(a0, 0.f) * L2E);
            float h1 = fmaxf(a1, 0.f) + ex2(fminf(a1, 0.f) * L2E);
            ph[q] = ok ? packh2(h0, h1) : 0u;
        }
        *(uint4*)(sm + OFF_AH + rbase + jb*16) = vh;
    }
}

__global__ __launch_bounds__(NT, 2)
void odefunc_mma(const float* __restrict__ zlp,
                 const float* __restrict__ W1, const float* __restrict__ b1,
                 const float* __restrict__ W2, const float* __restrict__ b2,
                 const float* __restrict__ W3, const float* __restrict__ b3,
                 float* __restrict__ out, int B, int ntiles)
{
    extern __shared__ char sm[];
    const uint32_t smb = smem_u32(sm);
    const int tid = threadIdx.x, w = tid >> 5, lane = tid & 31;

    float4* sTBL = (float4*)(sm + OFF_TBL);
    float*  sRSW = (float*)(sm + OFF_RSW);

    // ---------- per-CTA weight prep ----------
    for (int m = tid; m < 32; m += NT){
        *(float4*)(sm + OFF_L1 + m*16) = make_float4(W1[4*m], W1[4*m+2], W1[4*m+1], W1[4*m+3]);
        *(float2*)(sm + OFF_B1P + m*8) = make_float2(b1[2*m], b1[2*m+1]);
    }

    for (int idx = tid; idx < H*H; idx += NT){
        int n = idx >> 6, j = idx & 63;            // n = output neuron, j = input
        float w2 = W2[idx];
        float c  = fmaf(W1[2*j], W3[n], W1[2*j+1] * W3[H + n]);   // C[j][n]
        uint32_t off = (uint32_t)(n*RS + 2*j);
        *(__half*)(sm + OFF_W2H + off) = __float2half_rn(w2);
        *(__half*)(sm + OFF_MH  + off) = __float2half_rn(w2 * c);
    }
    if (tid < H){
        float s = 0.f;                             // rowsum of W2 (exact fp32)
        #pragma unroll 8
        for (int j = 0; j < H; j++) s += W2[tid*H + j];
        sRSW[tid] = s;
    }
    __syncthreads();
    if (tid < H){
        // a2 = W2*h + b2 = W2*h' + (b2 - rowsumW2);  t = M*min(h',1)  (rs folds away)
        sTBL[tid] = make_float4(b2[tid] - sRSW[tid], 0.f, W3[tid], W3[H + tid]);
    }
    if (tid == 0){                       // fold the epilogue "-1" of h2 into the output bias
        float sx = 0.f, sy = 0.f;
        #pragma unroll 8
        for (int k = 0; k < H; k++){ sx += W3[k]; sy += W3[H + k]; }
        *(float2*)(sm + OFF_ADJ) = make_float2(b3[0] - sx, b3[1] - sy);
    }
    __syncthreads();

    const float2 adj = *(const float2*)(sm + OFF_ADJ);

    // ldmatrix lane address components
    const int aRow  = (lane & 7) + ((lane >> 3) & 1) * 8;     // A x4: rows within 16
    const int aColB = (lane >> 4) * 16;
    const int bRow4 = (lane & 7) + ((lane >> 4) & 1) * 8;     // B x4: n within ng-pair
    const int bCol4 = ((lane >> 3) & 1) * 16;

    const uint32_t aAH  = smb + OFF_AH + (uint32_t)((w*32 + aRow)*RS + aColB);
    const uint32_t bW2  = smb + OFF_W2H + (uint32_t)(bRow4*RS + bCol4);
    const uint32_t bM   = smb + OFF_MH  + (uint32_t)(bRow4*RS + bCol4);
    const uint32_t rbase = (uint32_t)tid * RS;
    const int tstride = gridDim.x;

    // ---- prologue: fill A for the first tile ----
    int tile = blockIdx.x;
    if (tile < ntiles){
        int s = tile * TILE + tid;
        bool ok = (s < B);
        float z0 = 0.f, z1 = 0.f;
        if (ok){ z0 = zlp[3*s]; z1 = zlp[3*s + 1]; }
        fill_row(sm, rbase, pack2(z0, z0), pack2(z1, z1), ok);
    }

    for (; tile < ntiles; tile += tstride){
        const int base = tile * TILE;
        __syncwarp();

        // ---- drain A-plane into registers: both m-tiles, all kc (32 regs) ----
        uint32_t ah[2][4][4];
        #pragma unroll
        for (int mt = 0; mt < 2; mt++)
            #pragma unroll
            for (int kc = 0; kc < 4; kc++)
                ldm_x4(ah[mt][kc], aAH + (uint32_t)(mt*16*RS + kc*32));
        __syncwarp();   // all lanes' ldsm complete -> A plane reusable

        // ---- pipelined fill for the NEXT tile (overlaps with GEMM below) ----
        {
            int nt2 = tile + tstride;
            if (nt2 < ntiles){
                int s = nt2 * TILE + tid;
                bool ok = (s < B);
                float z0 = 0.f, z1 = 0.f;
                if (ok){ z0 = zlp[3*s]; z1 = zlp[3*s + 1]; }
                fill_row(sm, rbase, pack2(z0, z0), pack2(z1, z1), ok);
            }
        }

        // ---- warp-local GEMM for the CURRENT tile ----
        #pragma unroll
        for (int mt = 0; mt < 2; mt++){
            float o0[2] = {0.f, 0.f}, o1[2] = {0.f, 0.f}, tr[2] = {0.f, 0.f};

            #pragma unroll
            for (int half = 0; half < 2; half++){
                float dv[4][4], dt[4][4];
                #pragma unroll
                for (int ng = 0; ng < 4; ng++)
                    #pragma unroll
                    for (int e = 0; e < 4; e++){ dv[ng][e] = 0.f; dt[ng][e] = 0.f; }

                #pragma unroll
                for (int kc = 0; kc < 4; kc++){
                    uint32_t roff0 = (uint32_t)((half*32     )*RS + kc*32);
                    uint32_t roff1 = (uint32_t)((half*32 + 16)*RS + kc*32);
                    uint32_t bv[8], bm[8];
                    ldm_x4(bv,     bW2 + roff0);
                    ldm_x4(bv + 4, bW2 + roff1);
                    ldm_x4(bm,     bM  + roff0);
                    ldm_x4(bm + 4, bM  + roff1);
                    uint32_t nh[4];
                    #pragma unroll
                    for (int e = 0; e < 4; e++) nh[e] = hmin1(ah[mt][kc][e]);
                    #pragma unroll
                    for (int ng = 0; ng < 4; ng++){
                        mma_f16(dv[ng], ah[mt][kc], bv + 2*ng);   // W2 * h'
                        mma_f16(dt[ng], nh,         bm + 2*ng);   // M * min(h',1)
                    }
                }

                // ---- epilogue: a2 = dv + (b2-rsW2); e = elu'(a2); h2' = max+e ----
                #pragma unroll
                for (int ng = 0; ng < 4; ng++){
                    int n0 = half*32 + ng*8 + 2*(lane & 3);
                    float4 t0 = sTBL[n0], t1 = sTBL[n0 + 1];
                    #pragma unroll
                    for (int rr = 0; rr < 2; rr++){
                        float v0 = dv[ng][2*rr],     tv0 = dt[ng][2*rr];
                        float v1 = dv[ng][2*rr + 1], tv1 = dt[ng][2*rr + 1];
                        float a0 = v0 + t0.x;
                        float a1 = v1 + t1.x;
                        float e0 = ex2(fminf(a0, 0.f) * L2E);
                        float e1 = ex2(fminf(a1, 0.f) * L2E);
                        float h0 = fmaxf(a0, 0.f) + e0;     // = elu(a)+1
                        float h1 = fmaxf(a1, 0.f) + e1;
                        o0[rr] = fmaf(t0.z, h0, fmaf(t1.z, h1, o0[rr]));
                        o1[rr] = fmaf(t0.w, h0, fmaf(t1.w, h1, o1[rr]));
                        tr[rr] = fmaf(e0, tv0, fmaf(e1, tv1, tr[rr]));
                    }
                }
            }

            // ---- reduce across the 4 lanes of each row group, store (per mt) ----
            #pragma unroll
            for (int rr = 0; rr < 2; rr++){
                o0[rr] += __shfl_xor_sync(0xffffffffu, o0[rr], 1);
                o0[rr] += __shfl_xor_sync(0xffffffffu, o0[rr], 2);
                o1[rr] += __shfl_xor_sync(0xffffffffu, o1[rr], 1);
                o1[rr] += __shfl_xor_sync(0xffffffffu, o1[rr], 2);
                tr[rr] += __shfl_xor_sync(0xffffffffu, tr[rr], 1);
                tr[rr] += __shfl_xor_sync(0xffffffffu, tr[rr], 2);
            }
            if ((lane & 3) == 0){
                int g = lane >> 2;
                #pragma unroll
                for (int rr = 0; rr < 2; rr++){
                    int s2 = base + w*32 + mt*16 + g + rr*8;
                    if (s2 < B){
                        out[3*s2]     = o0[rr] + adj.x;
                        out[3*s2 + 1] = o1[rr] + adj.y;
                        out[3*s2 + 2] = -tr[rr];
                    }
                }
            }
        }
    }
}

extern "C" void kernel_launch(void* const* d_in, const int* in_sizes, int n_in,
                              void* d_out, int out_size)
{
    // metadata order: t, z_and_logp, W1, b1, W2, b2, W3, b3
    const float* zlp = (const float*)d_in[1];
    const float* W1  = (const float*)d_in[2];
    const float* b1  = (const float*)d_in[3];
    const float* W2  = (const float*)d_in[4];
    const float* b2  = (const float*)d_in[5];
    const float* W3  = (const float*)d_in[6];
    const float* b3  = (const float*)d_in[7];
    float* out = (float*)d_out;
    int B = in_sizes[1] / 3;
    int ntiles = (B + TILE - 1) / TILE;

    cudaFuncSetAttribute(odefunc_mma, cudaFuncAttributeMaxDynamicSharedMemorySize, SMEM_TOTAL);
    int grid = 296;               // 2 CTAs x 148 SMs, persistent
    if (grid > ntiles) grid = ntiles;
    odefunc_mma<<<grid, NT, SMEM_TOTAL>>>(zlp, W1, b1, W2, b2, W3, b3, out, B, ntiles);
}

// round 16
// speedup vs baseline: 1.5925x; 1.0173x over previous
#include <cuda_runtime.h>
#include <cuda_fp16.h>
#include <cstdint>

#define H 64
#define TILE 256
#define NT 256
#define RS 144                  // smem row stride (bytes): 9*16 -> conflict-free ldmatrix
#define L2E 1.4426950408889634f
#define LN2 0.6931471805599453f

typedef unsigned long long ull;

// ---- smem layout (bytes) ----
#define OFF_AH   0               // h+1 (fp16)      : 256 x 144 = 36864
#define OFF_W2H  36864           // W2 (fp16)       : 64 x 144
#define OFF_MH   46080           // M  (fp16)       : 64 x 144
#define OFF_TBL  55296           // float4[64]: (b2 - rowsumW2, unused, W3_0, W3_1)
#define OFF_L1   56320           // float4[32]: L2E*(w1a_0, w1a_1, w1b_0, w1b_1)
#define OFF_B1P  56832           // float2[32]: L2E*b1 pair
#define OFF_ADJ  57088           // float2: (b3_0 - sum W3_0, b3_1 - sum W3_1)
#define OFF_RSW  57096           // float[64] scratch (rowsum W2)
#define SMEM_TOTAL 57600

__device__ __forceinline__ uint32_t smem_u32(const void* p){
    uint32_t a;
    asm("{ .reg .u64 t; cvta.to.shared.u64 t, %1; cvt.u32.u64 %0, t; }" : "=r"(a) : "l"(p));
    return a;
}
__device__ __forceinline__ void ldm_x4(uint32_t* r, uint32_t addr){
    asm volatile("ldmatrix.sync.aligned.m8n8.x4.shared.b16 {%0,%1,%2,%3}, [%4];"
        : "=r"(r[0]),"=r"(r[1]),"=r"(r[2]),"=r"(r[3]) : "r"(addr));
}
__device__ __forceinline__ void mma_f16(float* d, const uint32_t* a, const uint32_t* b){
    asm volatile("mma.sync.aligned.m16n8k16.row.col.f32.f16.f16.f32 "
        "{%0,%1,%2,%3}, {%4,%5,%6,%7}, {%8,%9}, {%0,%1,%2,%3};"
        : "+f"(d[0]),"+f"(d[1]),"+f"(d[2]),"+f"(d[3])
        : "r"(a[0]),"r"(a[1]),"r"(a[2]),"r"(a[3]), "r"(b[0]),"r"(b[1]));
}
__device__ __forceinline__ ull pack2(float a, float b){
    ull v; asm("mov.b64 %0, {%1, %2};" : "=l"(v) : "f"(a), "f"(b)); return v;
}
__device__ __forceinline__ void unpack2(ull v, float &a, float &b){
    asm("mov.b64 {%0, %1}, %2;" : "=f"(a), "=f"(b) : "l"(v));
}
__device__ __forceinline__ void fma2(ull &d, ull a, ull b){
    asm("fma.rn.f32x2 %0, %1, %2, %0;" : "+l"(d) : "l"(a), "l"(b));
}
__device__ __forceinline__ float ex2(float x){
    float r; asm("ex2.approx.f32 %0, %1;" : "=f"(r) : "f"(x)); return r;
}
__device__ __forceinline__ uint32_t packh2(float a, float b){
    __half2 v = __floats2half2_rn(a, b);
    return *reinterpret_cast<uint32_t*>(&v);
}
// elementwise min(x, 1) on packed fp16: min(h',1) = min(h,0)+1
__device__ __forceinline__ uint32_t hmin1(uint32_t v){
    __half2 a = *reinterpret_cast<__half2*>(&v);
    __half2 one = __floats2half2_rn(1.f, 1.f);
    __half2 m = __hmin2(a, one);
    return *reinterpret_cast<uint32_t*>(&m);
}

__global__ __launch_bounds__(NT, 2)
void odefunc_mma(const float* __restrict__ zlp,
                 const float* __restrict__ W1, const float* __restrict__ b1,
                 const float* __restrict__ W2, const float* __restrict__ b2,
                 const float* __restrict__ W3, const float* __restrict__ b3,
                 float* __restrict__ out, int B, int ntiles)
{
    extern __shared__ char sm[];
    const uint32_t smb = smem_u32(sm);
    const int tid = threadIdx.x, w = tid >> 5, lane = tid & 31;

    float4* sTBL = (float4*)(sm + OFF_TBL);
    float*  sRSW = (float*)(sm + OFF_RSW);

    // ---------- per-CTA weight prep (layer-1 pre-scaled by log2(e)) ----------
    for (int m = tid; m < 32; m += NT){
        *(float4*)(sm + OFF_L1 + m*16) =
            make_float4(L2E*W1[4*m], L2E*W1[4*m+2], L2E*W1[4*m+1], L2E*W1[4*m+3]);
        *(float2*)(sm + OFF_B1P + m*8) = make_float2(L2E*b1[2*m], L2E*b1[2*m+1]);
    }

    for (int idx = tid; idx < H*H; idx += NT){
        int n = idx >> 6, j = idx & 63;            // n = output neuron, j = input
        float w2 = W2[idx];
        float c  = fmaf(W1[2*j], W3[n], W1[2*j+1] * W3[H + n]);   // C[j][n]
        uint32_t off = (uint32_t)(n*RS + 2*j);
        *(__half*)(sm + OFF_W2H + off) = __float2half_rn(w2);
        *(__half*)(sm + OFF_MH  + off) = __float2half_rn(w2 * c);
    }
    if (tid < H){
        float s = 0.f;                             // rowsum of W2 (exact fp32)
        #pragma unroll 8
        for (int j = 0; j < H; j++) s += W2[tid*H + j];
        sRSW[tid] = s;
    }
    __syncthreads();
    if (tid < H){
        // a2 = W2*h + b2 = W2*h' + (b2 - rowsumW2);  t = M*min(h',1)  (rs folds away)
        sTBL[tid] = make_float4(b2[tid] - sRSW[tid], 0.f, W3[tid], W3[H + tid]);
    }
    if (tid == 0){                       // fold the epilogue "-1" of h2 into the output bias
        float sx = 0.f, sy = 0.f;
        #pragma unroll 8
        for (int k = 0; k < H; k++){ sx += W3[k]; sy += W3[H + k]; }
        *(float2*)(sm + OFF_ADJ) = make_float2(b3[0] - sx, b3[1] - sy);
    }
    __syncthreads();

    const float2 adj = *(const float2*)(sm + OFF_ADJ);

    // ldmatrix lane address components
    const int aRow  = (lane & 7) + ((lane >> 3) & 1) * 8;     // A x4: rows within 16
    const int aColB = (lane >> 4) * 16;
    const int bRow4 = (lane & 7) + ((lane >> 4) & 1) * 8;     // B x4: n within ng-pair
    const int bCol4 = ((lane >> 3) & 1) * 16;

    const uint32_t aAH  = smb + OFF_AH + (uint32_t)((w*32 + aRow)*RS + aColB);
    const uint32_t bW2  = smb + OFF_W2H + (uint32_t)(bRow4*RS + bCol4);
    const uint32_t bM   = smb + OFF_MH  + (uint32_t)(bRow4*RS + bCol4);
    const uint32_t rbase = (uint32_t)tid * RS;

    for (int tile = blockIdx.x; tile < ntiles; tile += gridDim.x){
        const int base = tile * TILE;
        const int s = base + tid;
        const bool ok = (s < B);
        float z0 = 0.f, z1 = 0.f;
        if (ok){ z0 = zlp[3*s]; z1 = zlp[3*s + 1]; }
        const ull z0p = pack2(z0, z0), z1p = pack2(z1, z1);

        // ---- fill this thread's A row: a' = L2E*a; h' = max(a',0)*ln2 + ex2(min(a',0)) ----
        {
            #pragma unroll
            for (int jb = 0; jb < 8; jb++){
                uint4 vh;
                uint32_t* ph = (uint32_t*)&vh;
                #pragma unroll
                for (int q = 0; q < 4; q++){
                    int m = jb*4 + q;
                    ulonglong2 Lw = *(const ulonglong2*)(sm + OFF_L1 + m*16);
                    ull a = *(const ull*)(sm + OFF_B1P + m*8);
                    fma2(a, Lw.y, z1p);              // + (L2E*w1b) * z1
                    fma2(a, Lw.x, z0p);              // + (L2E*w1a) * z0
                    float a0, a1; unpack2(a, a0, a1);
                    float h0 = fmaf(fmaxf(a0, 0.f), LN2, ex2(fminf(a0, 0.f)));
                    float h1 = fmaf(fmaxf(a1, 0.f), LN2, ex2(fminf(a1, 0.f)));
                    ph[q] = ok ? packh2(h0, h1) : 0u;
                }
                *(uint4*)(sm + OFF_AH + rbase + jb*16) = vh;
            }
        }
        __syncwarp();

        float o0[2][2] = {{0,0},{0,0}}, o1[2][2] = {{0,0},{0,0}}, tr[2][2] = {{0,0},{0,0}};

        // ---- warp-local GEMM: half outer, both m-tiles share each B load ----
        #pragma unroll
        for (int half = 0; half < 2; half++){
            float dv[2][4][4], dt[2][4][4];
            #pragma unroll
            for (int mt = 0; mt < 2; mt++)
                #pragma unroll
                for (int ng = 0; ng < 4; ng++)
                    #pragma unroll
                    for (int e = 0; e < 4; e++){ dv[mt][ng][e] = 0.f; dt[mt][ng][e] = 0.f; }

            #pragma unroll
            for (int kc = 0; kc < 4; kc++){
                uint32_t roff0 = (uint32_t)((half*32     )*RS + kc*32);
                uint32_t roff1 = (uint32_t)((half*32 + 16)*RS + kc*32);
                uint32_t bv[8], bm[8];
                ldm_x4(bv,     bW2 + roff0);
                ldm_x4(bv + 4, bW2 + roff1);
                ldm_x4(bm,     bM  + roff0);
                ldm_x4(bm + 4, bM  + roff1);
                #pragma unroll
                for (int mt = 0; mt < 2; mt++){
                    uint32_t ah[4], nh[4];
                    ldm_x4(ah, aAH + (uint32_t)(mt*16*RS + kc*32));
                    #pragma unroll
                    for (int e = 0; e < 4; e++) nh[e] = hmin1(ah[e]);
                    #pragma unroll
                    for (int ng = 0; ng < 4; ng++){
                        mma_f16(dv[mt][ng], ah, bv + 2*ng);   // W2 * h'
                        mma_f16(dt[mt][ng], nh, bm + 2*ng);   // M * min(h',1)
                    }
                }
            }

            // ---- epilogue: a2 = dv + (b2-rsW2); e = elu'(a2); h2' = max+e ----
            #pragma unroll
            for (int ng = 0; ng < 4; ng++){
                int n0 = half*32 + ng*8 + 2*(lane & 3);
                float4 t0 = sTBL[n0], t1 = sTBL[n0 + 1];
                #pragma unroll
                for (int mt = 0; mt < 2; mt++)
                    #pragma unroll
                    for (int rr = 0; rr < 2; rr++){
                        float v0 = dv[mt][ng][2*rr],     tv0 = dt[mt][ng][2*rr];
                        float v1 = dv[mt][ng][2*rr + 1], tv1 = dt[mt][ng][2*rr + 1];
                        float a0 = v0 + t0.x;
                        float a1 = v1 + t1.x;
                        float e0 = ex2(fminf(a0, 0.f) * L2E);
                        float e1 = ex2(fminf(a1, 0.f) * L2E);
                        float h0 = fmaxf(a0, 0.f) + e0;     // = elu(a)+1
                        float h1 = fmaxf(a1, 0.f) + e1;
                        o0[mt][rr] = fmaf(t0.z, h0, fmaf(t1.z, h1, o0[mt][rr]));
                        o1[mt][rr] = fmaf(t0.w, h0, fmaf(t1.w, h1, o1[mt][rr]));
                        tr[mt][rr] = fmaf(e0, tv0, fmaf(e1, tv1, tr[mt][rr]));
                    }
            }
        }

        // ---- reduce across the 4 lanes of each row group, store ----
        #pragma unroll
        for (int mt = 0; mt < 2; mt++)
            #pragma unroll
            for (int rr = 0; rr < 2; rr++){
                o0[mt][rr] += __shfl_xor_sync(0xffffffffu, o0[mt][rr], 1);
                o0[mt][rr] += __shfl_xor_sync(0xffffffffu, o0[mt][rr], 2);
                o1[mt][rr] += __shfl_xor_sync(0xffffffffu, o1[mt][rr], 1);
                o1[mt][rr] += __shfl_xor_sync(0xffffffffu, o1[mt][rr], 2);
                tr[mt][rr] += __shfl_xor_sync(0xffffffffu, tr[mt][rr], 1);
                tr[mt][rr] += __shfl_xor_sync(0xffffffffu, tr[mt][rr], 2);
            }
        if ((lane & 3) == 0){
            int g = lane >> 2;
            #pragma unroll
            for (int mt = 0; mt < 2; mt++)
                #pragma unroll
                for (int rr = 0; rr < 2; rr++){
                    int s2 = base + w*32 + mt*16 + g + rr*8;
                    if (s2 < B){
                        out[3*s2]     = o0[mt][rr] + adj.x;
                        out[3*s2 + 1] = o1[mt][rr] + adj.y;
                        out[3*s2 + 2] = -tr[mt][rr];
                    }
                }
        }
        __syncwarp();   // GEMM reads of A done before next tile's fill overwrites
    }
}

extern "C" void kernel_launch(void* const* d_in, const int* in_sizes, int n_in,
                              void* d_out, int out_size)
{
    // metadata order: t, z_and_logp, W1, b1, W2, b2, W3, b3
    const float* zlp = (const float*)d_in[1];
    const float* W1  = (const float*)d_in[2];
    const float* b1  = (const float*)d_in[3];
    const float* W2  = (const float*)d_in[4];
    const float* b2  = (const float*)d_in[5];
    const float* W3  = (const float*)d_in[6];
    const float* b3  = (const float*)d_in[7];
    float* out = (float*)d_out;
    int B = in_sizes[1] / 3;
    int ntiles = (B + TILE - 1) / TILE;

    cudaFuncSetAttribute(odefunc_mma, cudaFuncAttributeMaxDynamicSharedMemorySize, SMEM_TOTAL);
    int grid = 296;               // 2 CTAs x 148 SMs, persistent
    if (grid > ntiles) grid = ntiles;
    odefunc_mma<<<grid, NT, SMEM_TOTAL>>>(zlp, W1, b1, W2, b2, W3, b3, out, B, ntiles);
}